// round 3
// baseline (speedup 1.0000x reference)
#include <cuda_runtime.h>
#include <math.h>

// Fused SSIM loss, single kernel: separable 11x11 Gaussian, 5 moment maps,
// epilogue, global mean + finalize via block counter (last block writes out).
// im1, im2: (32,3,512,512) fp32; window: (3,1,11,11) fp32 outer(g,g).

#define TX 32
#define TY 64
#define HALO 5
#define RX 42          // TX + 10
#define RXP 44         // padded (16B-aligned vec loads)
#define RY 74          // TY + 10
#define IMG 512
#define NPLANES 96
#define NPIX 25165824.0
#define NBLOCKS (16 * 8 * 96)   // (512/32) * (512/64) * 96 = 12288

// smem layout (bytes)
#define OFF_S12   0
#define SZ_S12    (RY * RXP * 8)            // 26048
#define OFF_HBME  (OFF_S12 + SZ_S12)        // 26048
#define SZ_HBME   (RY * TX * 16)            // 37888
#define OFF_HB12  (OFF_HBME + SZ_HBME)      // 63936
#define SZ_HB12   (RY * TX * 4)             // 9472
#define OFF_GGP   (OFF_HB12 + SZ_HB12)      // 73408
#define OFF_WS    (OFF_GGP + 11 * 8)        // 73496
#define SMEM_TOT  (OFF_WS + 8 * 4)          // 73528

typedef unsigned long long u64;

__device__ __forceinline__ u64 pk2(float a, float b) {
    u64 r; asm("mov.b64 %0,{%1,%2};" : "=l"(r) : "f"(a), "f"(b)); return r;
}
__device__ __forceinline__ void unpk(u64 v, float& a, float& b) {
    asm("mov.b64 {%0,%1},%2;" : "=f"(a), "=f"(b) : "l"(v));
}
__device__ __forceinline__ u64 fma2(u64 a, u64 b, u64 c) {
    u64 d; asm("fma.rn.f32x2 %0,%1,%2,%3;" : "=l"(d) : "l"(a), "l"(b), "l"(c)); return d;
}
__device__ __forceinline__ u64 mul2(u64 a, u64 b) {
    u64 d; asm("mul.rn.f32x2 %0,%1,%2;" : "=l"(d) : "l"(a), "l"(b)); return d;
}
__device__ __forceinline__ u64 add2(u64 a, u64 b) {
    u64 d; asm("add.rn.f32x2 %0,%1,%2;" : "=l"(d) : "l"(a), "l"(b)); return d;
}

__device__ double g_accum = 0.0;
__device__ unsigned int g_ctr = 0;

__global__ void __launch_bounds__(256, 2)
ssim_main_kernel(const float* __restrict__ im1,
                 const float* __restrict__ im2,
                 const float* __restrict__ window,
                 float* __restrict__ out)
{
    extern __shared__ char sm_raw[];
    u64    (*s12)[RXP] = (u64   (*)[RXP])(sm_raw + OFF_S12);
    float4 (*hbME)[TX] = (float4(*)[TX])(sm_raw + OFF_HBME);
    float  (*hb12)[TX] = (float (*)[TX])(sm_raw + OFF_HB12);
    u64    *ggp        = (u64*)(sm_raw + OFF_GGP);
    float  *warpsum    = (float*)(sm_raw + OFF_WS);

    const int tid = threadIdx.x;

    // 1-D Gaussian from outer-product window: g[k] = w[5][k]/sqrt(w[5][5])
    if (tid < 11) {
        float g5 = sqrtf(window[5 * 11 + 5]);
        float g  = window[5 * 11 + tid] / g5;
        ggp[tid] = pk2(g, g);
    }

    const int x0 = blockIdx.x * TX;
    const int y0 = blockIdx.y * TY;
    const long plane = (long)blockIdx.z * (IMG * IMG);
    const float* __restrict__ p1 = im1 + plane;
    const float* __restrict__ p2 = im2 + plane;

    // ---- load 74x42 packed tile with zero padding ----
    for (int idx = tid; idx < RY * RX; idx += 256) {
        int r = idx / RX;
        int c = idx - r * RX;
        int gy = y0 + r - HALO;
        int gx = x0 + c - HALO;
        float v1 = 0.0f, v2 = 0.0f;
        if ((unsigned)gy < (unsigned)IMG && (unsigned)gx < (unsigned)IMG) {
            int o = gy * IMG + gx;
            v1 = p1[o];
            v2 = p2[o];
        }
        s12[r][c] = pk2(v1, v2);
    }
    __syncthreads();

    u64 G[11];
    #pragma unroll
    for (int k = 0; k < 11; k++) G[k] = ggp[k];

    // ---- horizontal pass: 74 rows x 8 groups of 4 cols ----
    for (int it = tid; it < RY * 8; it += 256) {
        int r  = it >> 3;
        int c0 = (it & 7) * 4;
        u64 x[14];
        const ulonglong2* p = (const ulonglong2*)&s12[r][c0];
        #pragma unroll
        for (int i = 0; i < 7; i++) {
            ulonglong2 q = p[i];
            x[2 * i]     = q.x;
            x[2 * i + 1] = q.y;
        }
        #pragma unroll
        for (int j = 0; j < 4; j++) {
            u64 aM = 0, aE = 0;
            float a12 = 0.0f;
            #pragma unroll
            for (int k = 0; k < 11; k++) {
                u64 v = x[j + k];
                u64 t = mul2(G[k], v);      // (g*v1, g*v2)
                aM = add2(aM, t);
                aE = fma2(t, v, aE);        // (g*v1^2, g*v2^2)
                float tlo, thi, v1, v2;
                unpk(t, tlo, thi);
                unpk(v, v1, v2);
                a12 = fmaf(tlo, v2, a12);   // g*v1*v2
            }
            float mlo, mhi, elo, ehi;
            unpk(aM, mlo, mhi);
            unpk(aE, elo, ehi);
            hbME[r][c0 + j] = make_float4(mlo, mhi, elo, ehi);
            hb12[r][c0 + j] = a12;
        }
    }
    __syncthreads();

    // ---- vertical pass: thread handles 8 rows of one column ----
    const int x  = tid & 31;
    const int yb = (tid >> 5) * 8;

    u64 accM[8], accE[8], acc12p[4];
    #pragma unroll
    for (int j = 0; j < 8; j++) { accM[j] = 0; accE[j] = 0; }
    #pragma unroll
    for (int j = 0; j < 4; j++) acc12p[j] = 0;

    float h_prev = 0.0f;
    #pragma unroll
    for (int i = 0; i < 18; i++) {
        float4 me = hbME[yb + i][x];
        u64 m = pk2(me.x, me.y);
        u64 e = pk2(me.z, me.w);
        float hv = hb12[yb + i][x];
        #pragma unroll
        for (int j = 0; j < 8; j++) {
            int k = i - j;
            if (k >= 0 && k <= 10) {
                accM[j] = fma2(G[k], m, accM[j]);
                accE[j] = fma2(G[k], e, accE[j]);
            }
        }
        if (i >= 1) {
            u64 pr = pk2(h_prev, hv);       // rows (i-1, i)
            #pragma unroll
            for (int jp = 0; jp < 4; jp++) {
                int k = (i - 1) - 2 * jp;
                if (k >= 0 && k <= 10)
                    acc12p[jp] = fma2(G[k], pr, acc12p[jp]);
            }
        }
        h_prev = hv;
    }

    // ---- SSIM epilogue ----
    const float C1 = 1e-4f;
    const float C2 = 9e-4f;
    float lsum = 0.0f;
    #pragma unroll
    for (int j = 0; j < 8; j++) {
        float m1, m2, e11, e22, plo, phi;
        unpk(accM[j], m1, m2);
        unpk(accE[j], e11, e22);
        unpk(acc12p[j >> 1], plo, phi);
        float e12 = (j & 1) ? phi : plo;
        float m1s = m1 * m1;
        float m2s = m2 * m2;
        float m12 = m1 * m2;
        float num = (2.0f * m12 + C1) * (2.0f * (e12 - m12) + C2);
        float den = (m1s + m2s + C1) * ((e11 - m1s) + (e22 - m2s) + C2);
        lsum += __fdividef(num, den);
    }

    // ---- block reduction ----
    #pragma unroll
    for (int o = 16; o > 0; o >>= 1)
        lsum += __shfl_down_sync(0xffffffffu, lsum, o);
    if ((tid & 31) == 0) warpsum[tid >> 5] = lsum;
    __syncthreads();
    if (tid == 0) {
        float t = 0.f;
        #pragma unroll
        for (int i = 0; i < 8; i++) t += warpsum[i];
        atomicAdd(&g_accum, (double)t);
        __threadfence();
        unsigned old = atomicAdd(&g_ctr, 1u);
        if (old == NBLOCKS - 1) {
            __threadfence();
            double a = *(volatile double*)&g_accum;
            out[0] = (float)(-a / NPIX);
            *(volatile double*)&g_accum = 0.0;
            *(volatile unsigned int*)&g_ctr = 0u;
            __threadfence();
        }
    }
}

extern "C" void kernel_launch(void* const* d_in, const int* in_sizes, int n_in,
                              void* d_out, int out_size)
{
    const float* im1 = (const float*)d_in[0];
    const float* im2 = (const float*)d_in[1];
    const float* win = (const float*)d_in[2];
    float* out = (float*)d_out;

    cudaFuncSetAttribute(ssim_main_kernel,
                         cudaFuncAttributeMaxDynamicSharedMemorySize, SMEM_TOT);
    dim3 grid(IMG / TX, IMG / TY, NPLANES);
    ssim_main_kernel<<<grid, 256, SMEM_TOT>>>(im1, im2, win, out);
}

// round 4
// speedup vs baseline: 1.7622x; 1.7622x over previous
#include <cuda_runtime.h>
#include <math.h>

// Fused SSIM loss, single kernel. Separable 11x11 Gaussian via 2-pass in smem,
// packed f32x2 math, precomputed v1*v2 plane, block-counter finalize.
// im1, im2: (32,3,512,512) fp32; window: (3,1,11,11) fp32 outer(g,g).

#define TX 32
#define TY 32
#define HALO 5
#define RX 42
#define RXP 44          // padded row stride (16B-aligned)
#define RY 42
#define IMG 512
#define NPLANES 96
#define NPIX 25165824.0
#define NBLOCKS (16 * 16 * 96)      // 24576

// dynamic smem layout (bytes)
#define OFF_S12   0
#define SZ_S12    (RY * RXP * 8)               // 14784
#define OFF_PV    (OFF_S12 + SZ_S12)
#define SZ_PV     (RY * RXP * 4)               // 7392
#define OFF_HBM   (OFF_PV + SZ_PV)
#define SZ_HBM    (RY * TX * 8)                // 10752
#define OFF_HBE   (OFF_HBM + SZ_HBM)
#define SZ_HBE    (RY * TX * 8)                // 10752
#define OFF_HB12  (OFF_HBE + SZ_HBE)
#define SZ_HB12   (RY * TX * 4)                // 5376
#define OFF_GGP   (OFF_HB12 + SZ_HB12)
#define OFF_WS    (OFF_GGP + 11 * 8)
#define SMEM_TOT  (OFF_WS + 8 * 4)             // ~49.2 KB

typedef unsigned long long u64;

__device__ __forceinline__ u64 pk2(float a, float b) {
    u64 r; asm("mov.b64 %0,{%1,%2};" : "=l"(r) : "f"(a), "f"(b)); return r;
}
__device__ __forceinline__ void unpk(u64 v, float& a, float& b) {
    asm("mov.b64 {%0,%1},%2;" : "=f"(a), "=f"(b) : "l"(v));
}
__device__ __forceinline__ u64 fma2(u64 a, u64 b, u64 c) {
    u64 d; asm("fma.rn.f32x2 %0,%1,%2,%3;" : "=l"(d) : "l"(a), "l"(b), "l"(c)); return d;
}
__device__ __forceinline__ u64 mul2(u64 a, u64 b) {
    u64 d; asm("mul.rn.f32x2 %0,%1,%2;" : "=l"(d) : "l"(a), "l"(b)); return d;
}
__device__ __forceinline__ u64 add2(u64 a, u64 b) {
    u64 d; asm("add.rn.f32x2 %0,%1,%2;" : "=l"(d) : "l"(a), "l"(b)); return d;
}

__device__ double g_accum = 0.0;
__device__ unsigned int g_ctr = 0;

__global__ void __launch_bounds__(256, 4)
ssim_main_kernel(const float* __restrict__ im1,
                 const float* __restrict__ im2,
                 const float* __restrict__ window,
                 float* __restrict__ out)
{
    extern __shared__ char sm_raw[];
    u64   (*s12)[RXP]  = (u64  (*)[RXP])(sm_raw + OFF_S12);
    float (*pv)[RXP]   = (float(*)[RXP])(sm_raw + OFF_PV);
    u64   (*hbM)[TX]   = (u64  (*)[TX])(sm_raw + OFF_HBM);
    u64   (*hbE)[TX]   = (u64  (*)[TX])(sm_raw + OFF_HBE);
    float (*hb12)[TX]  = (float(*)[TX])(sm_raw + OFF_HB12);
    u64   *ggp         = (u64*)(sm_raw + OFF_GGP);
    float *warpsum     = (float*)(sm_raw + OFF_WS);

    const int tid = threadIdx.x;

    // 1-D Gaussian from outer-product window: g[k] = w[5][k]/sqrt(w[5][5])
    if (tid < 11) {
        float g5 = sqrtf(window[5 * 11 + 5]);
        float g  = window[5 * 11 + tid] / g5;
        ggp[tid] = pk2(g, g);
    }

    const int x0 = blockIdx.x * TX;
    const int y0 = blockIdx.y * TY;
    const long plane = (long)blockIdx.z * (IMG * IMG);
    const float* __restrict__ p1 = im1 + plane;
    const float* __restrict__ p2 = im2 + plane;

    // ---- load 42x42 packed tile + product plane, zero padded ----
    #pragma unroll
    for (int i = 0; i < 7; i++) {
        int idx = tid + i * 256;
        if (idx < RY * RX) {
            int r = idx / RX;
            int c = idx - r * RX;
            int gy = y0 + r - HALO;
            int gx = x0 + c - HALO;
            float v1 = 0.0f, v2 = 0.0f;
            if ((unsigned)gy < (unsigned)IMG && (unsigned)gx < (unsigned)IMG) {
                int o = gy * IMG + gx;
                v1 = p1[o];
                v2 = p2[o];
            }
            s12[r][c] = pk2(v1, v2);
            pv[r][c]  = v1 * v2;
        }
    }
    __syncthreads();

    u64 G[11];
    #pragma unroll
    for (int k = 0; k < 11; k++) G[k] = ggp[k];

    // ---- horizontal pass: 42 rows x 8 groups of 4 cols = 336 items ----
    for (int it = tid; it < RY * 8; it += 256) {
        int r  = it >> 3;
        int c0 = (it & 7) * 4;

        u64 x[14];
        {
            const ulonglong2* p = (const ulonglong2*)&s12[r][c0];
            #pragma unroll
            for (int i = 0; i < 7; i++) {
                ulonglong2 q = p[i];
                x[2 * i]     = q.x;
                x[2 * i + 1] = q.y;
            }
        }
        float pvv[16];
        {
            const float4* p = (const float4*)&pv[r][c0];
            #pragma unroll
            for (int i = 0; i < 4; i++) {
                float4 q = p[i];
                pvv[4 * i]     = q.x;
                pvv[4 * i + 1] = q.y;
                pvv[4 * i + 2] = q.z;
                pvv[4 * i + 3] = q.w;
            }
        }

        // mu / E streams (packed over the two images)
        #pragma unroll
        for (int j = 0; j < 4; j++) {
            u64 aM = 0, aE = 0;
            #pragma unroll
            for (int k = 0; k < 11; k++) {
                u64 v = x[j + k];
                u64 t = mul2(G[k], v);
                aM = add2(aM, t);
                aE = fma2(t, v, aE);
            }
            hbM[r][c0 + j] = aM;
            hbE[r][c0 + j] = aE;
        }

        // sigma12 stream, packed over adjacent column pairs
        {
            u64 a01 = 0, a23 = 0;
            #pragma unroll
            for (int i = 0; i < 13; i++) {
                u64 pr = pk2(pvv[i], pvv[i + 1]);
                if (i <= 10) a01 = fma2(G[i], pr, a01);
                if (i >= 2)  a23 = fma2(G[i - 2], pr, a23);
            }
            float o0, o1, o2, o3;
            unpk(a01, o0, o1);
            unpk(a23, o2, o3);
            hb12[r][c0 + 0] = o0;
            hb12[r][c0 + 1] = o1;
            hb12[r][c0 + 2] = o2;
            hb12[r][c0 + 3] = o3;
        }
    }
    __syncthreads();

    // ---- vertical pass: each thread computes 4 rows of one column ----
    const int x  = tid & 31;
    const int yb = (tid >> 5) * 4;

    u64 accM[4] = {0, 0, 0, 0};
    u64 accE[4] = {0, 0, 0, 0};
    u64 a01 = 0, a23 = 0;

    {
        u64 rowv[14];
        #pragma unroll
        for (int i = 0; i < 14; i++) rowv[i] = hbM[yb + i][x];
        #pragma unroll
        for (int j = 0; j < 4; j++)
            #pragma unroll
            for (int k = 0; k < 11; k++)
                accM[j] = fma2(G[k], rowv[j + k], accM[j]);

        #pragma unroll
        for (int i = 0; i < 14; i++) rowv[i] = hbE[yb + i][x];
        #pragma unroll
        for (int j = 0; j < 4; j++)
            #pragma unroll
            for (int k = 0; k < 11; k++)
                accE[j] = fma2(G[k], rowv[j + k], accE[j]);
    }
    {
        float h[14];
        #pragma unroll
        for (int i = 0; i < 14; i++) h[i] = hb12[yb + i][x];
        #pragma unroll
        for (int i = 0; i < 13; i++) {
            u64 pr = pk2(h[i], h[i + 1]);      // rows (i, i+1)
            if (i <= 10) a01 = fma2(G[i], pr, a01);
            if (i >= 2)  a23 = fma2(G[i - 2], pr, a23);
        }
    }

    // ---- SSIM epilogue ----
    const float C1 = 1e-4f;
    const float C2 = 9e-4f;
    float e12v[4];
    unpk(a01, e12v[0], e12v[1]);
    unpk(a23, e12v[2], e12v[3]);
    float lsum = 0.0f;
    #pragma unroll
    for (int j = 0; j < 4; j++) {
        float m1, m2, e11, e22;
        unpk(accM[j], m1, m2);
        unpk(accE[j], e11, e22);
        float m1s = m1 * m1;
        float m2s = m2 * m2;
        float m12 = m1 * m2;
        float num = (2.0f * m12 + C1) * (2.0f * (e12v[j] - m12) + C2);
        float den = (m1s + m2s + C1) * ((e11 - m1s) + (e22 - m2s) + C2);
        lsum += __fdividef(num, den);
    }

    // ---- block reduction + global accumulate + finalize ----
    #pragma unroll
    for (int o = 16; o > 0; o >>= 1)
        lsum += __shfl_down_sync(0xffffffffu, lsum, o);
    if ((tid & 31) == 0) warpsum[tid >> 5] = lsum;
    __syncthreads();
    if (tid == 0) {
        float t = 0.f;
        #pragma unroll
        for (int i = 0; i < 8; i++) t += warpsum[i];
        atomicAdd(&g_accum, (double)t);
        __threadfence();
        unsigned old = atomicAdd(&g_ctr, 1u);
        if (old == NBLOCKS - 1) {
            __threadfence();
            double a = *(volatile double*)&g_accum;
            out[0] = (float)(-a / NPIX);
            *(volatile double*)&g_accum = 0.0;
            *(volatile unsigned int*)&g_ctr = 0u;
            __threadfence();
        }
    }
}

extern "C" void kernel_launch(void* const* d_in, const int* in_sizes, int n_in,
                              void* d_out, int out_size)
{
    const float* im1 = (const float*)d_in[0];
    const float* im2 = (const float*)d_in[1];
    const float* win = (const float*)d_in[2];
    float* out = (float*)d_out;

    cudaFuncSetAttribute(ssim_main_kernel,
                         cudaFuncAttributeMaxDynamicSharedMemorySize, SMEM_TOT);
    dim3 grid(IMG / TX, IMG / TY, NPLANES);
    ssim_main_kernel<<<grid, 256, SMEM_TOT>>>(im1, im2, win, out);
}

// round 6
// speedup vs baseline: 1.8434x; 1.0461x over previous
#include <cuda_runtime.h>
#include <math.h>

// Fused SSIM loss, single kernel. Separable 11x11 Gaussian, packed f32x2,
// conflict-free smem layouts, float4-merged h-pass moments, shared squares.
// im1, im2: (32,3,512,512) fp32; window: (3,1,11,11) fp32 outer(g,g).
// (Resubmission of Round-5 kernel: previous bench hit an infra failure.)

#define TX 32
#define TY 32
#define HALO 5
#define RX 42
#define RY 42
#define IMG 512
#define NPLANES 96
#define NPIX 25165824.0
#define NBLOCKS (16 * 16 * 96)   // 24576

// strides chosen for conflict-free access
#define S12_STR 46     // u64 units;  92 words/row  (28 mod 32)
#define PV_STR  44     // float units; 44 words/row (12 mod 32)
#define HB_STR  33     // float4 units; 132 words/row (4 mod 32); also hb12 floats

// dynamic smem layout (bytes)
#define OFF_S12   0
#define SZ_S12    (RY * S12_STR * 8)            // 15456
#define OFF_PV    (OFF_S12 + SZ_S12)
#define SZ_PV     (RY * PV_STR * 4)             // 7392
#define OFF_HBME  (OFF_PV + SZ_PV)
#define SZ_HBME   (RY * HB_STR * 16)            // 22176
#define OFF_HB12  (OFF_HBME + SZ_HBME)
#define SZ_HB12   (RY * HB_STR * 4)             // 5544
#define OFF_GGP   (OFF_HB12 + SZ_HB12)
#define OFF_WS    (OFF_GGP + 11 * 8)
#define SMEM_TOT  (OFF_WS + 8 * 4)              // ~50.7 KB -> 4 blocks/SM

typedef unsigned long long u64;

__device__ __forceinline__ u64 pk2(float a, float b) {
    u64 r; asm("mov.b64 %0,{%1,%2};" : "=l"(r) : "f"(a), "f"(b)); return r;
}
__device__ __forceinline__ void unpk(u64 v, float& a, float& b) {
    asm("mov.b64 {%0,%1},%2;" : "=f"(a), "=f"(b) : "l"(v));
}
__device__ __forceinline__ u64 fma2(u64 a, u64 b, u64 c) {
    u64 d; asm("fma.rn.f32x2 %0,%1,%2,%3;" : "=l"(d) : "l"(a), "l"(b), "l"(c)); return d;
}
__device__ __forceinline__ u64 mul2(u64 a, u64 b) {
    u64 d; asm("mul.rn.f32x2 %0,%1,%2;" : "=l"(d) : "l"(a), "l"(b)); return d;
}

__device__ double g_accum = 0.0;
__device__ unsigned int g_ctr = 0;

__global__ void __launch_bounds__(256, 4)
ssim_main_kernel(const float* __restrict__ im1,
                 const float* __restrict__ im2,
                 const float* __restrict__ window,
                 float* __restrict__ out)
{
    extern __shared__ char sm_raw[];
    u64*    s12    = (u64*)   (sm_raw + OFF_S12);
    float*  pv     = (float*) (sm_raw + OFF_PV);
    float4* hbME   = (float4*)(sm_raw + OFF_HBME);
    float*  hb12   = (float*) (sm_raw + OFF_HB12);
    u64*    ggp    = (u64*)   (sm_raw + OFF_GGP);
    float*  warpsum= (float*) (sm_raw + OFF_WS);

    const int tid = threadIdx.x;

    // 1-D Gaussian from outer-product window: g[k] = w[5][k]/sqrt(w[5][5])
    if (tid < 11) {
        float g5 = sqrtf(window[5 * 11 + 5]);
        float g  = window[5 * 11 + tid] / g5;
        ggp[tid] = pk2(g, g);
    }

    const int x0 = blockIdx.x * TX;
    const int y0 = blockIdx.y * TY;
    const long plane = (long)blockIdx.z * (IMG * IMG);
    const float* __restrict__ p1 = im1 + plane;
    const float* __restrict__ p2 = im2 + plane;

    // ---- load 42x42 packed tile + product plane, zero padded ----
    #pragma unroll
    for (int i = 0; i < 7; i++) {
        int idx = tid + i * 256;
        if (idx < RY * RX) {
            int r = idx / RX;
            int c = idx - r * RX;
            int gy = y0 + r - HALO;
            int gx = x0 + c - HALO;
            float v1 = 0.0f, v2 = 0.0f;
            if ((unsigned)gy < (unsigned)IMG && (unsigned)gx < (unsigned)IMG) {
                int o = gy * IMG + gx;
                v1 = p1[o];
                v2 = p2[o];
            }
            s12[r * S12_STR + c] = pk2(v1, v2);
            pv [r * PV_STR  + c] = v1 * v2;
        }
    }
    __syncthreads();

    u64 G[11];
    #pragma unroll
    for (int k = 0; k < 11; k++) G[k] = ggp[k];

    // ---- horizontal pass: items mapped so consecutive tid -> consecutive r ----
    for (int it = tid; it < RY * 8; it += 256) {
        int r  = it % RY;
        int c0 = (it / RY) * 4;

        u64 aM[4] = {0, 0, 0, 0};
        u64 aE[4] = {0, 0, 0, 0};

        const ulonglong2* ps = (const ulonglong2*)(s12 + r * S12_STR + c0);
        #pragma unroll
        for (int ii = 0; ii < 7; ii++) {
            ulonglong2 q = ps[ii];
            #pragma unroll
            for (int h = 0; h < 2; h++) {
                const int i = 2 * ii + h;
                u64 v = h ? q.y : q.x;
                u64 s = mul2(v, v);
                #pragma unroll
                for (int j = 0; j < 4; j++) {
                    const int k = i - j;
                    if (k >= 0 && k <= 10) {
                        aM[j] = fma2(G[k], v, aM[j]);
                        aE[j] = fma2(G[k], s, aE[j]);
                    }
                }
            }
        }

        // sigma12 stream over precomputed products, packed column pairs
        float pvv[16];
        {
            const float4* pp = (const float4*)(pv + r * PV_STR + c0);
            #pragma unroll
            for (int i = 0; i < 4; i++) {
                float4 q = pp[i];
                pvv[4 * i]     = q.x;
                pvv[4 * i + 1] = q.y;
                pvv[4 * i + 2] = q.z;
                pvv[4 * i + 3] = q.w;
            }
        }
        u64 a01 = 0, a23 = 0;
        #pragma unroll
        for (int i = 0; i < 13; i++) {
            u64 pr = pk2(pvv[i], pvv[i + 1]);
            if (i <= 10) a01 = fma2(G[i], pr, a01);
            if (i >= 2)  a23 = fma2(G[i - 2], pr, a23);
        }

        // stores: float4-merged moments + scalar sigma12
        #pragma unroll
        for (int j = 0; j < 4; j++) {
            float ml, mh, el, eh;
            unpk(aM[j], ml, mh);
            unpk(aE[j], el, eh);
            hbME[r * HB_STR + c0 + j] = make_float4(ml, mh, el, eh);
        }
        float o0, o1, o2, o3;
        unpk(a01, o0, o1);
        unpk(a23, o2, o3);
        hb12[r * HB_STR + c0 + 0] = o0;
        hb12[r * HB_STR + c0 + 1] = o1;
        hb12[r * HB_STR + c0 + 2] = o2;
        hb12[r * HB_STR + c0 + 3] = o3;
    }
    __syncthreads();

    // ---- vertical pass: each thread computes 4 rows of one column ----
    const int x  = tid & 31;
    const int yb = (tid >> 5) * 4;

    u64 accM[4] = {0, 0, 0, 0};
    u64 accE[4] = {0, 0, 0, 0};
    u64 a01 = 0, a23 = 0;
    float hprev = 0.0f;

    #pragma unroll
    for (int i = 0; i < 14; i++) {
        float4 q = hbME[(yb + i) * HB_STR + x];
        u64 m = pk2(q.x, q.y);
        u64 e = pk2(q.z, q.w);
        #pragma unroll
        for (int j = 0; j < 4; j++) {
            const int k = i - j;
            if (k >= 0 && k <= 10) {
                accM[j] = fma2(G[k], m, accM[j]);
                accE[j] = fma2(G[k], e, accE[j]);
            }
        }
        float hv = hb12[(yb + i) * HB_STR + x];
        if (i >= 1) {
            const int ip = i - 1;                 // pair (h[ip], h[ip+1])
            u64 pr = pk2(hprev, hv);
            if (ip <= 10) a01 = fma2(G[ip], pr, a01);
            if (ip >= 2)  a23 = fma2(G[ip - 2], pr, a23);
        }
        hprev = hv;
    }

    // ---- SSIM epilogue ----
    const float C1 = 1e-4f;
    const float C2 = 9e-4f;
    float e12v[4];
    unpk(a01, e12v[0], e12v[1]);
    unpk(a23, e12v[2], e12v[3]);
    float lsum = 0.0f;
    #pragma unroll
    for (int j = 0; j < 4; j++) {
        float m1, m2, e11, e22;
        unpk(accM[j], m1, m2);
        unpk(accE[j], e11, e22);
        float m1s = m1 * m1;
        float m2s = m2 * m2;
        float m12 = m1 * m2;
        float num = (2.0f * m12 + C1) * (2.0f * (e12v[j] - m12) + C2);
        float den = (m1s + m2s + C1) * ((e11 - m1s) + (e22 - m2s) + C2);
        lsum += __fdividef(num, den);
    }

    // ---- block reduction + global accumulate + finalize ----
    #pragma unroll
    for (int o = 16; o > 0; o >>= 1)
        lsum += __shfl_down_sync(0xffffffffu, lsum, o);
    if ((tid & 31) == 0) warpsum[tid >> 5] = lsum;
    __syncthreads();
    if (tid == 0) {
        float t = 0.f;
        #pragma unroll
        for (int i = 0; i < 8; i++) t += warpsum[i];
        atomicAdd(&g_accum, (double)t);
        __threadfence();
        unsigned old = atomicAdd(&g_ctr, 1u);
        if (old == NBLOCKS - 1) {
            __threadfence();
            double a = *(volatile double*)&g_accum;
            out[0] = (float)(-a / NPIX);
            *(volatile double*)&g_accum = 0.0;
            *(volatile unsigned int*)&g_ctr = 0u;
            __threadfence();
        }
    }
}

extern "C" void kernel_launch(void* const* d_in, const int* in_sizes, int n_in,
                              void* d_out, int out_size)
{
    const float* im1 = (const float*)d_in[0];
    const float* im2 = (const float*)d_in[1];
    const float* win = (const float*)d_in[2];
    float* out = (float*)d_out;

    cudaFuncSetAttribute(ssim_main_kernel,
                         cudaFuncAttributeMaxDynamicSharedMemorySize, SMEM_TOT);
    dim3 grid(IMG / TX, IMG / TY, NPLANES);
    ssim_main_kernel<<<grid, 256, SMEM_TOT>>>(im1, im2, win, out);
}

// round 7
// speedup vs baseline: 1.9353x; 1.0499x over previous
#include <cuda_runtime.h>
#include <math.h>

// Fused SSIM loss, single kernel. Separable 11x11 Gaussian, packed f32x2,
// conflict-free smem, no product plane (recomputed from register pairs),
// 5 blocks/SM occupancy target.
// im1, im2: (32,3,512,512) fp32; window: (3,1,11,11) fp32 outer(g,g).

#define TX 32
#define TY 32
#define HALO 5
#define RX 42
#define RY 42
#define IMG 512
#define NPLANES 96
#define NPIX 25165824.0
#define NBLOCKS (16 * 16 * 96)   // 24576

// conflict-free strides
#define S12_STR 46     // u64 units;  92 words/row  (28 mod 32)
#define HB_STR  33     // float4 units; 132 words/row (4 mod 32); also hb12 floats

// dynamic smem layout (bytes)
#define OFF_S12   0
#define SZ_S12    (RY * S12_STR * 8)            // 15456
#define OFF_HBME  (OFF_S12 + SZ_S12)
#define SZ_HBME   (RY * HB_STR * 16)            // 22176
#define OFF_HB12  (OFF_HBME + SZ_HBME)
#define SZ_HB12   (RY * HB_STR * 4)             // 5544
#define OFF_GGP   (OFF_HB12 + SZ_HB12)
#define OFF_WS    (OFF_GGP + 11 * 8)
#define SMEM_TOT  (OFF_WS + 8 * 4)              // ~43.3 KB -> 5 blocks/SM

typedef unsigned long long u64;

__device__ __forceinline__ u64 pk2(float a, float b) {
    u64 r; asm("mov.b64 %0,{%1,%2};" : "=l"(r) : "f"(a), "f"(b)); return r;
}
__device__ __forceinline__ void unpk(u64 v, float& a, float& b) {
    asm("mov.b64 {%0,%1},%2;" : "=f"(a), "=f"(b) : "l"(v));
}
__device__ __forceinline__ u64 fma2(u64 a, u64 b, u64 c) {
    u64 d; asm("fma.rn.f32x2 %0,%1,%2,%3;" : "=l"(d) : "l"(a), "l"(b), "l"(c)); return d;
}
__device__ __forceinline__ u64 mul2(u64 a, u64 b) {
    u64 d; asm("mul.rn.f32x2 %0,%1,%2;" : "=l"(d) : "l"(a), "l"(b)); return d;
}

__device__ double g_accum = 0.0;
__device__ unsigned int g_ctr = 0;

__global__ void __launch_bounds__(256, 5)
ssim_main_kernel(const float* __restrict__ im1,
                 const float* __restrict__ im2,
                 const float* __restrict__ window,
                 float* __restrict__ out)
{
    extern __shared__ char sm_raw[];
    u64*    s12    = (u64*)   (sm_raw + OFF_S12);
    float4* hbME   = (float4*)(sm_raw + OFF_HBME);
    float*  hb12   = (float*) (sm_raw + OFF_HB12);
    u64*    ggp    = (u64*)   (sm_raw + OFF_GGP);
    float*  warpsum= (float*) (sm_raw + OFF_WS);

    const int tid = threadIdx.x;

    // 1-D Gaussian from outer-product window: g[k] = w[5][k]/sqrt(w[5][5])
    if (tid < 11) {
        float g5 = sqrtf(window[5 * 11 + 5]);
        float g  = window[5 * 11 + tid] / g5;
        ggp[tid] = pk2(g, g);
    }

    const int x0 = blockIdx.x * TX;
    const int y0 = blockIdx.y * TY;
    const long plane = (long)blockIdx.z * (IMG * IMG);
    const float* __restrict__ p1 = im1 + plane;
    const float* __restrict__ p2 = im2 + plane;

    // ---- load 42x42 packed tile, zero padded ----
    #pragma unroll
    for (int i = 0; i < 7; i++) {
        int idx = tid + i * 256;
        if (idx < RY * RX) {
            int r = idx / RX;
            int c = idx - r * RX;
            int gy = y0 + r - HALO;
            int gx = x0 + c - HALO;
            float v1 = 0.0f, v2 = 0.0f;
            if ((unsigned)gy < (unsigned)IMG && (unsigned)gx < (unsigned)IMG) {
                int o = gy * IMG + gx;
                v1 = p1[o];
                v2 = p2[o];
            }
            s12[r * S12_STR + c] = pk2(v1, v2);
        }
    }
    __syncthreads();

    u64 G[11];
    #pragma unroll
    for (int k = 0; k < 11; k++) G[k] = ggp[k];

    // ---- horizontal pass: consecutive tid -> consecutive r (conflict-free) ----
    for (int it = tid; it < RY * 8; it += 256) {
        int r  = it % RY;
        int c0 = (it / RY) * 4;

        u64 aM[4] = {0, 0, 0, 0};
        u64 aE[4] = {0, 0, 0, 0};
        float pvv[14];

        const ulonglong2* ps = (const ulonglong2*)(s12 + r * S12_STR + c0);
        #pragma unroll
        for (int ii = 0; ii < 7; ii++) {
            ulonglong2 q = ps[ii];
            #pragma unroll
            for (int h = 0; h < 2; h++) {
                const int i = 2 * ii + h;
                u64 v = h ? q.y : q.x;
                u64 s = mul2(v, v);
                float v1, v2;
                unpk(v, v1, v2);          // free: register-pair halves
                pvv[i] = v1 * v2;
                #pragma unroll
                for (int j = 0; j < 4; j++) {
                    const int k = i - j;
                    if (k >= 0 && k <= 10) {
                        aM[j] = fma2(G[k], v, aM[j]);
                        aE[j] = fma2(G[k], s, aE[j]);
                    }
                }
            }
        }

        // sigma12 stream: packed adjacent column pairs
        u64 a01 = 0, a23 = 0;
        #pragma unroll
        for (int i = 0; i < 13; i++) {
            u64 pr = pk2(pvv[i], pvv[i + 1]);
            if (i <= 10) a01 = fma2(G[i], pr, a01);
            if (i >= 2)  a23 = fma2(G[i - 2], pr, a23);
        }

        // stores: float4-merged moments + scalar sigma12
        #pragma unroll
        for (int j = 0; j < 4; j++) {
            float ml, mh, el, eh;
            unpk(aM[j], ml, mh);
            unpk(aE[j], el, eh);
            hbME[r * HB_STR + c0 + j] = make_float4(ml, mh, el, eh);
        }
        float o0, o1, o2, o3;
        unpk(a01, o0, o1);
        unpk(a23, o2, o3);
        hb12[r * HB_STR + c0 + 0] = o0;
        hb12[r * HB_STR + c0 + 1] = o1;
        hb12[r * HB_STR + c0 + 2] = o2;
        hb12[r * HB_STR + c0 + 3] = o3;
    }
    __syncthreads();

    // ---- vertical pass: each thread computes 4 rows of one column ----
    const int x  = tid & 31;
    const int yb = (tid >> 5) * 4;

    u64 accM[4] = {0, 0, 0, 0};
    u64 accE[4] = {0, 0, 0, 0};
    u64 a01 = 0, a23 = 0;
    float hprev = 0.0f;

    #pragma unroll
    for (int i = 0; i < 14; i++) {
        float4 q = hbME[(yb + i) * HB_STR + x];
        u64 m = pk2(q.x, q.y);
        u64 e = pk2(q.z, q.w);
        #pragma unroll
        for (int j = 0; j < 4; j++) {
            const int k = i - j;
            if (k >= 0 && k <= 10) {
                accM[j] = fma2(G[k], m, accM[j]);
                accE[j] = fma2(G[k], e, accE[j]);
            }
        }
        float hv = hb12[(yb + i) * HB_STR + x];
        if (i >= 1) {
            const int ip = i - 1;
            u64 pr = pk2(hprev, hv);
            if (ip <= 10) a01 = fma2(G[ip], pr, a01);
            if (ip >= 2)  a23 = fma2(G[ip - 2], pr, a23);
        }
        hprev = hv;
    }

    // ---- SSIM epilogue ----
    const float C1 = 1e-4f;
    const float C2 = 9e-4f;
    float e12v[4];
    unpk(a01, e12v[0], e12v[1]);
    unpk(a23, e12v[2], e12v[3]);
    float lsum = 0.0f;
    #pragma unroll
    for (int j = 0; j < 4; j++) {
        float m1, m2, e11, e22;
        unpk(accM[j], m1, m2);
        unpk(accE[j], e11, e22);
        float m1s = m1 * m1;
        float m2s = m2 * m2;
        float m12 = m1 * m2;
        float num = (2.0f * m12 + C1) * (2.0f * (e12v[j] - m12) + C2);
        float den = (m1s + m2s + C1) * ((e11 - m1s) + (e22 - m2s) + C2);
        lsum += __fdividef(num, den);
    }

    // ---- block reduction + global accumulate + finalize ----
    #pragma unroll
    for (int o = 16; o > 0; o >>= 1)
        lsum += __shfl_down_sync(0xffffffffu, lsum, o);
    if ((tid & 31) == 0) warpsum[tid >> 5] = lsum;
    __syncthreads();
    if (tid == 0) {
        float t = 0.f;
        #pragma unroll
        for (int i = 0; i < 8; i++) t += warpsum[i];
        atomicAdd(&g_accum, (double)t);
        __threadfence();
        unsigned old = atomicAdd(&g_ctr, 1u);
        if (old == NBLOCKS - 1) {
            __threadfence();
            double a = *(volatile double*)&g_accum;
            out[0] = (float)(-a / NPIX);
            *(volatile double*)&g_accum = 0.0;
            *(volatile unsigned int*)&g_ctr = 0u;
            __threadfence();
        }
    }
}

extern "C" void kernel_launch(void* const* d_in, const int* in_sizes, int n_in,
                              void* d_out, int out_size)
{
    const float* im1 = (const float*)d_in[0];
    const float* im2 = (const float*)d_in[1];
    const float* win = (const float*)d_in[2];
    float* out = (float*)d_out;

    cudaFuncSetAttribute(ssim_main_kernel,
                         cudaFuncAttributeMaxDynamicSharedMemorySize, SMEM_TOT);
    dim3 grid(IMG / TX, IMG / TY, NPLANES);
    ssim_main_kernel<<<grid, 256, SMEM_TOT>>>(im1, im2, win, out);
}

// round 9
// speedup vs baseline: 2.5150x; 1.2995x over previous
#include <cuda_runtime.h>
#include <math.h>

// Fused SSIM loss in the (w,d)=(v1+v2, v1-v2) basis: 2 packed conv streams
// replace 5 scalar streams. Separable 11x11 Gaussian, packed f32x2,
// conflict-free smem, single kernel with block-counter finalize.
// im1, im2: (32,3,512,512) fp32; window: (3,1,11,11) fp32 outer(g,g).
// (Resubmission: Round-8 bench hit a broker/container infra failure.)

#define TX 32
#define TY 32
#define HALO 5
#define RX 42
#define RY 42
#define IMG 512
#define NPLANES 96
#define NPIX 25165824.0
#define NBLOCKS (16 * 16 * 96)   // 24576

// conflict-free strides
#define S12_STR 46     // u64 units;  92 words/row  (28 mod 32)
#define HB_STR  33     // float4 units; 132 words/row (4 mod 32)

// dynamic smem layout (bytes)
#define OFF_S12   0
#define SZ_S12    (RY * S12_STR * 8)            // 15456
#define OFF_HB    (OFF_S12 + SZ_S12)
#define SZ_HB     (RY * HB_STR * 16)            // 22176
#define OFF_GGP   (OFF_HB + SZ_HB)
#define OFF_WS    (OFF_GGP + 11 * 8)
#define SMEM_TOT  (OFF_WS + 8 * 4)              // ~37.8 KB

typedef unsigned long long u64;

__device__ __forceinline__ u64 pk2(float a, float b) {
    u64 r; asm("mov.b64 %0,{%1,%2};" : "=l"(r) : "f"(a), "f"(b)); return r;
}
__device__ __forceinline__ void unpk(u64 v, float& a, float& b) {
    asm("mov.b64 {%0,%1},%2;" : "=f"(a), "=f"(b) : "l"(v));
}
__device__ __forceinline__ u64 fma2(u64 a, u64 b, u64 c) {
    u64 d; asm("fma.rn.f32x2 %0,%1,%2,%3;" : "=l"(d) : "l"(a), "l"(b), "l"(c)); return d;
}
__device__ __forceinline__ u64 mul2(u64 a, u64 b) {
    u64 d; asm("mul.rn.f32x2 %0,%1,%2;" : "=l"(d) : "l"(a), "l"(b)); return d;
}

__device__ double g_accum = 0.0;
__device__ unsigned int g_ctr = 0;

__global__ void __launch_bounds__(256, 5)
ssim_main_kernel(const float* __restrict__ im1,
                 const float* __restrict__ im2,
                 const float* __restrict__ window,
                 float* __restrict__ out)
{
    extern __shared__ char sm_raw[];
    u64*    swd    = (u64*)   (sm_raw + OFF_S12);   // packed (w,d) input tile
    float4* hb     = (float4*)(sm_raw + OFF_HB);    // (Mw,Md,Sw,Sd) h-moments
    u64*    ggp    = (u64*)   (sm_raw + OFF_GGP);
    float*  warpsum= (float*) (sm_raw + OFF_WS);

    const int tid = threadIdx.x;

    // 1-D Gaussian from outer-product window: g[k] = w[5][k]/sqrt(w[5][5])
    if (tid < 11) {
        float g5 = sqrtf(window[5 * 11 + 5]);
        float g  = window[5 * 11 + tid] / g5;
        ggp[tid] = pk2(g, g);
    }

    const int x0 = blockIdx.x * TX;
    const int y0 = blockIdx.y * TY;
    const long plane = (long)blockIdx.z * (IMG * IMG);
    const float* __restrict__ p1 = im1 + plane;
    const float* __restrict__ p2 = im2 + plane;

    // ---- load 42x42 tile as packed (w,d), zero padded ----
    #pragma unroll
    for (int i = 0; i < 7; i++) {
        int idx = tid + i * 256;
        if (idx < RY * RX) {
            int r = idx / RX;
            int c = idx - r * RX;
            int gy = y0 + r - HALO;
            int gx = x0 + c - HALO;
            float v1 = 0.0f, v2 = 0.0f;
            if ((unsigned)gy < (unsigned)IMG && (unsigned)gx < (unsigned)IMG) {
                int o = gy * IMG + gx;
                v1 = p1[o];
                v2 = p2[o];
            }
            swd[r * S12_STR + c] = pk2(v1 + v2, v1 - v2);
        }
    }
    __syncthreads();

    u64 G[11];
    #pragma unroll
    for (int k = 0; k < 11; k++) G[k] = ggp[k];

    // ---- horizontal pass: consecutive tid -> consecutive r (conflict-free) ----
    for (int it = tid; it < RY * 8; it += 256) {
        int r  = it % RY;
        int c0 = (it / RY) * 4;

        u64 aM[4] = {0, 0, 0, 0};     // conv of (w,d)
        u64 aS[4] = {0, 0, 0, 0};     // conv of (w^2,d^2)

        const ulonglong2* ps = (const ulonglong2*)(swd + r * S12_STR + c0);
        #pragma unroll
        for (int ii = 0; ii < 7; ii++) {
            ulonglong2 q = ps[ii];
            #pragma unroll
            for (int h = 0; h < 2; h++) {
                const int i = 2 * ii + h;
                u64 v = h ? q.y : q.x;
                u64 s = mul2(v, v);
                #pragma unroll
                for (int j = 0; j < 4; j++) {
                    const int k = i - j;
                    if (k >= 0 && k <= 10) {
                        aM[j] = fma2(G[k], v, aM[j]);
                        aS[j] = fma2(G[k], s, aS[j]);
                    }
                }
            }
        }

        #pragma unroll
        for (int j = 0; j < 4; j++) {
            float mw, md, sw, sd;
            unpk(aM[j], mw, md);
            unpk(aS[j], sw, sd);
            hb[r * HB_STR + c0 + j] = make_float4(mw, md, sw, sd);
        }
    }
    __syncthreads();

    // ---- vertical pass: each thread computes 4 rows of one column ----
    const int x  = tid & 31;
    const int yb = (tid >> 5) * 4;

    u64 accM[4] = {0, 0, 0, 0};
    u64 accS[4] = {0, 0, 0, 0};

    #pragma unroll
    for (int i = 0; i < 14; i++) {
        float4 q = hb[(yb + i) * HB_STR + x];
        u64 m = pk2(q.x, q.y);
        u64 s = pk2(q.z, q.w);
        #pragma unroll
        for (int j = 0; j < 4; j++) {
            const int k = i - j;
            if (k >= 0 && k <= 10) {
                accM[j] = fma2(G[k], m, accM[j]);
                accS[j] = fma2(G[k], s, accS[j]);
            }
        }
    }

    // ---- SSIM epilogue in (w,d) basis ----
    // P=Mw^2, Q=Md^2:
    //   2*mu1mu2        = (P-Q)/2
    //   mu1^2+mu2^2     = (P+Q)/2
    //   2*sigma12       = (Sw-Sd)/2 - (P-Q)/2
    //   sig1sq+sig2sq   = (Sw+Sd)/2 - (P+Q)/2
    const float C1 = 1e-4f;
    const float C2 = 9e-4f;
    float lsum = 0.0f;
    #pragma unroll
    for (int j = 0; j < 4; j++) {
        float mw, md, sw, sd;
        unpk(accM[j], mw, md);
        unpk(accS[j], sw, sd);
        float P = mw * mw;
        float Q = md * md;
        float pd = 0.5f * (P - Q);            // 2*mu1*mu2
        float ps = 0.5f * (P + Q);            // mu1^2 + mu2^2
        float num = (pd + C1) * (0.5f * (sw - sd) - pd + C2);
        float den = (ps + C1) * (0.5f * (sw + sd) - ps + C2);
        lsum += __fdividef(num, den);
    }

    // ---- block reduction + global accumulate + finalize ----
    #pragma unroll
    for (int o = 16; o > 0; o >>= 1)
        lsum += __shfl_down_sync(0xffffffffu, lsum, o);
    if ((tid & 31) == 0) warpsum[tid >> 5] = lsum;
    __syncthreads();
    if (tid == 0) {
        float t = 0.f;
        #pragma unroll
        for (int i = 0; i < 8; i++) t += warpsum[i];
        atomicAdd(&g_accum, (double)t);
        __threadfence();
        unsigned old = atomicAdd(&g_ctr, 1u);
        if (old == NBLOCKS - 1) {
            __threadfence();
            double a = *(volatile double*)&g_accum;
            out[0] = (float)(-a / NPIX);
            *(volatile double*)&g_accum = 0.0;
            *(volatile unsigned int*)&g_ctr = 0u;
            __threadfence();
        }
    }
}

extern "C" void kernel_launch(void* const* d_in, const int* in_sizes, int n_in,
                              void* d_out, int out_size)
{
    const float* im1 = (const float*)d_in[0];
    const float* im2 = (const float*)d_in[1];
    const float* win = (const float*)d_in[2];
    float* out = (float*)d_out;

    cudaFuncSetAttribute(ssim_main_kernel,
                         cudaFuncAttributeMaxDynamicSharedMemorySize, SMEM_TOT);
    dim3 grid(IMG / TX, IMG / TY, NPLANES);
    ssim_main_kernel<<<grid, 256, SMEM_TOT>>>(im1, im2, win, out);
}